// round 14
// baseline (speedup 1.0000x reference)
#include <cuda_runtime.h>
#include <cuda_fp16.h>
#include <cstdint>

#define BATCH 32
#define NTOK  1024
#define CH    512
#define DQKD  64

// ---------------------------------------------------------------------------
// Device-global scratch (fp16 operands)
// ---------------------------------------------------------------------------
__device__ __align__(128) __half g_xh[(size_t)BATCH * NTOK * CH];     // 32 MB
__device__ __align__(128) __half g_wt[640 * CH];                      // W^T [n][k]
__device__ __align__(128) __half g_qh[(size_t)BATCH * NTOK * DQKD];
__device__ __align__(128) __half g_kh[(size_t)BATCH * NTOK * DQKD];
__device__ __align__(128) __half g_vh[(size_t)BATCH * NTOK * CH];     // V [b][m][c]
__device__ __align__(128) __half g_p[(size_t)BATCH * NTOK * NTOK];    // 64 MB P~ (unnormalized)
__device__ __align__(128) float  g_inv[(size_t)BATCH * NTOK];         // 1/rowsum

// ---------------------------------------------------------------------------
// PTX helpers (baseline ISA: compiles for compute_103)
// ---------------------------------------------------------------------------
__device__ __forceinline__ uint32_t smem_u32(const void* p) {
    uint32_t a;
    asm("{ .reg .u64 t; cvta.to.shared.u64 t, %1; cvt.u32.u64 %0, t; }" : "=r"(a) : "l"(p));
    return a;
}
__device__ __forceinline__ void cp16(uint32_t dst, const void* src) {
    asm volatile("cp.async.cg.shared.global [%0], [%1], 16;" :: "r"(dst), "l"(src));
}
#define CP_COMMIT() asm volatile("cp.async.commit_group;" ::: "memory")
#define CP_WAIT1()  asm volatile("cp.async.wait_group 1;" ::: "memory")

__device__ __forceinline__ void ldm_x4(uint32_t* r, uint32_t addr) {
    asm volatile("ldmatrix.sync.aligned.m8n8.x4.shared.b16 {%0,%1,%2,%3}, [%4];"
                 : "=r"(r[0]), "=r"(r[1]), "=r"(r[2]), "=r"(r[3]) : "r"(addr));
}
__device__ __forceinline__ void ldm_x2(uint32_t* r, uint32_t addr) {
    asm volatile("ldmatrix.sync.aligned.m8n8.x2.shared.b16 {%0,%1}, [%2];"
                 : "=r"(r[0]), "=r"(r[1]) : "r"(addr));
}
__device__ __forceinline__ void ldm_x4_trans(uint32_t* r, uint32_t addr) {
    asm volatile("ldmatrix.sync.aligned.m8n8.x4.trans.shared.b16 {%0,%1,%2,%3}, [%4];"
                 : "=r"(r[0]), "=r"(r[1]), "=r"(r[2]), "=r"(r[3]) : "r"(addr));
}
__device__ __forceinline__ void mma_f16(float* c, const uint32_t* a, const uint32_t* b) {
    asm volatile(
        "mma.sync.aligned.m16n8k16.row.col.f32.f16.f16.f32 "
        "{%0,%1,%2,%3}, {%4,%5,%6,%7}, {%8,%9}, {%0,%1,%2,%3};"
        : "+f"(c[0]), "+f"(c[1]), "+f"(c[2]), "+f"(c[3])
        : "r"(a[0]), "r"(a[1]), "r"(a[2]), "r"(a[3]), "r"(b[0]), "r"(b[1]));
}

// ---------------------------------------------------------------------------
// qkv tiling: CTA 128x128, BK=64, 2-stage, rows 144 B, 128 thr (warps 2x2).
// ---------------------------------------------------------------------------
#define ROW_B   144
#define TILE_B  (128 * ROW_B)        // 18432
#define OB_OFF  TILE_B
#define STAGE_B (2 * TILE_B)         // 36864
#define SMEM_B  (2 * STAGE_B)        // 73728

// av: A = P [128 tok][64 k] rows 144 B; B = V [64 k][128 c] rows 272 B
#define AV_BROW   272
#define AV_BTILE  (64 * AV_BROW)     // 17408
#define AV_OB     TILE_B
#define AV_STAGE  (TILE_B + AV_BTILE)   // 35840
#define AV_INV    (2 * AV_STAGE)        // 71680 (128 floats)
#define AV_SMEM   (AV_INV + 512)        // 72192

// probs: q [32][64] rows 144 B; k double-buffered [128][64] rows 144 B;
// fp16 staging [32 rows][272 B]; partial sums [32 rows][4 warps]
#define PR_Q      0
#define PR_QSZ    (32 * ROW_B)                    // 4608
#define PR_K      PR_QSZ
#define PR_KSZ    (128 * ROW_B)                   // 18432
#define PR_ST     (PR_K + 2 * PR_KSZ)             // 41472
#define PR_STROW  272
#define PR_STSZ   (32 * PR_STROW)                 // 8704
#define PR_SUM    (PR_ST + PR_STSZ)               // 50176
#define PR_SMEM   (PR_SUM + 512)                  // 50688

// exp shift: P~ = exp(s*0.125 - SHIFT). SHIFT=4 keeps all P~ in fp16 NORMAL
// range (subnormal only if s < -45; overflow only if s > 120 -- neither occurs).
#define EXP_SHIFT 4.0f

// ---------------------------------------------------------------------------
// Combined prep kernel
// ---------------------------------------------------------------------------
#define CONVX_BLOCKS 16384
#define CONVW_BLOCKS 1280

__global__ void conv_kernel(const float* __restrict__ x,
                            const float* __restrict__ wq,
                            const float* __restrict__ wk,
                            const float* __restrict__ wv)
{
    if (blockIdx.x < CONVX_BLOCKS) {
        size_t i = ((size_t)blockIdx.x * 256 + threadIdx.x) * 4;
        float4 v = *(const float4*)(x + i);
        __half2 a, b;
        a.x = __float2half(v.x); a.y = __float2half(v.y);
        b.x = __float2half(v.z); b.y = __float2half(v.w);
        *(__half2*)(g_xh + i)     = a;
        *(__half2*)(g_xh + i + 2) = b;
    } else {
        int idx = (blockIdx.x - CONVX_BLOCKS) * 256 + threadIdx.x;   // 640*512
        int n = idx >> 9, k = idx & 511;
        float v;
        if (n < 64)        v = wq[k * DQKD + n];
        else if (n < 128)  v = wk[k * DQKD + (n - 64)];
        else               v = wv[k * CH + (n - 128)];
        g_wt[idx] = __float2half(v);
    }
}

// ---------------------------------------------------------------------------
// Kernel 1: QKV projection.  M=32768, N=640, K=512. grid (5, 256).
// 128 thr, 4 warps (2x2), warp tile 64x64, 3 CTAs/SM.  (unchanged from R13)
// ---------------------------------------------------------------------------
__global__ void __launch_bounds__(128, 3)
qkv_tc_kernel(const float* __restrict__ bq, const float* __restrict__ bk,
              const float* __restrict__ bv)
{
    extern __shared__ char dsmem[];
    const uint32_t sb = smem_u32(dsmem);
    const int m0 = blockIdx.y * 128;
    const int n0 = blockIdx.x * 128;
    const int tid = threadIdx.x;
    const int wid = tid >> 5, lane = tid & 31;
    const int mw = (wid >> 1) * 64, nw = (wid & 1) * 64;

    const __half* gA = g_xh + (size_t)m0 * CH;
    const __half* gB = g_wt + (size_t)n0 * CH;

    const uint32_t a_l = (uint32_t)((lane & 15) * ROW_B + (lane >> 4) * 16);
    const uint32_t b_l = (uint32_t)((lane & 7) * ROW_B + ((lane >> 3) & 1) * 16);

    auto load_stage = [&](int chunk, int st) {
        const int k0 = chunk * 64;
        const uint32_t base = sb + (uint32_t)st * STAGE_B;
        #pragma unroll
        for (int t = 0; t < 8; t++) {
            int u = tid + t * 128;
            int row = u >> 3, seg = u & 7;
            uint32_t so = base + (uint32_t)(row * ROW_B + seg * 16);
            cp16(so,          gA + (size_t)row * CH + k0 + seg * 8);
            cp16(so + OB_OFF, gB + (size_t)row * CH + k0 + seg * 8);
        }
        CP_COMMIT();
    };

    float acc[4][8][4] = {};
    load_stage(0, 0);

    for (int c = 0; c < 8; c++) {
        if (c + 1 < 8) load_stage(c + 1, (c + 1) & 1);
        else           CP_COMMIT();
        CP_WAIT1();
        __syncthreads();

        const uint32_t stb = sb + (uint32_t)(c & 1) * STAGE_B;
        #pragma unroll
        for (int kk = 0; kk < 64; kk += 16) {
            uint32_t bf[8][2];
            #pragma unroll
            for (int nb = 0; nb < 8; nb++)
                ldm_x2(bf[nb], stb + OB_OFF + (uint32_t)((nw + nb * 8) * ROW_B + kk * 2) + b_l);
            #pragma unroll
            for (int mb = 0; mb < 4; mb++) {
                uint32_t af[4];
                ldm_x4(af, stb + (uint32_t)((mw + mb * 16) * ROW_B + kk * 2) + a_l);
                #pragma unroll
                for (int nb = 0; nb < 8; nb++)
                    mma_f16(acc[mb][nb], af, bf[nb]);
            }
        }
        __syncthreads();
    }

    const int gid = lane >> 2, tig = lane & 3;
    #pragma unroll
    for (int mb = 0; mb < 4; mb++)
        #pragma unroll
        for (int nb = 0; nb < 8; nb++)
            #pragma unroll
            for (int h = 0; h < 2; h++) {
                int row = m0 + mw + mb * 16 + gid + h * 8;
                int col = n0 + nw + nb * 8 + tig * 2;
                float b0, b1;
                if (col < 64)       { b0 = bq[col];        b1 = bq[col + 1]; }
                else if (col < 128) { b0 = bk[col - 64];   b1 = bk[col - 63]; }
                else                { b0 = bv[col - 128];  b1 = bv[col - 127]; }
                __half2 hv;
                hv.x = __float2half(acc[mb][nb][h * 2 + 0] + b0);
                hv.y = __float2half(acc[mb][nb][h * 2 + 1] + b1);
                if (col < 64)
                    *(__half2*)(g_qh + (size_t)row * DQKD + col) = hv;
                else if (col < 128)
                    *(__half2*)(g_kh + (size_t)row * DQKD + (col - 64)) = hv;
                else
                    *(__half2*)(g_vh + (size_t)row * CH + (col - 128)) = hv;
            }
}

// ---------------------------------------------------------------------------
// Kernel 2: FUSED scores + exp -> unnormalized P~ (fp16) + row inv-sums.
// (unchanged)
// ---------------------------------------------------------------------------
__global__ void __launch_bounds__(256, 4)
probs_kernel()
{
    extern __shared__ char dsmem[];
    const uint32_t sb = smem_u32(dsmem);
    __half* St = (__half*)(dsmem + PR_ST);
    float* Sum = (float*)(dsmem + PR_SUM);

    const int tid = threadIdx.x;
    const int wid = tid >> 5, lane = tid & 31;
    const int b = blockIdx.y;
    const int i0 = blockIdx.x * 32;

    const __half* gq = g_qh + ((size_t)b * NTOK + i0) * DQKD;
    const __half* gk = g_kh + (size_t)b * NTOK * DQKD;

    {
        int row = tid >> 3, seg = tid & 7;
        cp16(sb + PR_Q + (uint32_t)(row * ROW_B + seg * 16),
             gq + (size_t)row * DQKD + seg * 8);
        #pragma unroll
        for (int t = 0; t < 4; t++) {
            int u = tid + t * 256;
            int r = u >> 3, s = u & 7;
            cp16(sb + PR_K + (uint32_t)(r * ROW_B + s * 16),
                 gk + (size_t)r * DQKD + s * 8);
        }
        CP_COMMIT();
    }

    const int mw = (wid >> 2) * 16;
    const int nw = (wid & 3) * 32;
    const uint32_t a_l = (uint32_t)((lane & 15) * ROW_B + (lane >> 4) * 16);
    const uint32_t b_l = (uint32_t)((lane & 7) * ROW_B + ((lane >> 3) & 1) * 16);
    const int gid = lane >> 2, tig = lane & 3;

    uint32_t af[4][4];
    bool a_loaded = false;
    float psum0 = 0.f, psum1 = 0.f;

    for (int j = 0; j < 8; j++) {
        if (j + 1 < 8) {
            const __half* gkn = gk + (size_t)(j + 1) * 128 * DQKD;
            const uint32_t kb = sb + PR_K + (uint32_t)(((j + 1) & 1) * PR_KSZ);
            #pragma unroll
            for (int t = 0; t < 4; t++) {
                int u = tid + t * 256;
                int r = u >> 3, s = u & 7;
                cp16(kb + (uint32_t)(r * ROW_B + s * 16), gkn + (size_t)r * DQKD + s * 8);
            }
            CP_COMMIT();
        } else CP_COMMIT();
        CP_WAIT1();
        __syncthreads();

        if (!a_loaded) {
            #pragma unroll
            for (int kk = 0; kk < 4; kk++)
                ldm_x4(af[kk], sb + PR_Q + (uint32_t)(mw * ROW_B + kk * 32) + a_l);
            a_loaded = true;
        }

        const uint32_t kbb = sb + PR_K + (uint32_t)((j & 1) * PR_KSZ);
        float acc[4][4] = {};
        #pragma unroll
        for (int kk = 0; kk < 4; kk++) {
            #pragma unroll
            for (int nb = 0; nb < 4; nb++) {
                uint32_t bf[2];
                ldm_x2(bf, kbb + (uint32_t)((nw + nb * 8) * ROW_B + kk * 32) + b_l);
                mma_f16(acc[nb], af[kk], bf);
            }
        }
        #pragma unroll
        for (int nb = 0; nb < 4; nb++) {
            float e0 = __expf(fmaf(acc[nb][0], 0.125f, -EXP_SHIFT));
            float e1 = __expf(fmaf(acc[nb][1], 0.125f, -EXP_SHIFT));
            float e2 = __expf(fmaf(acc[nb][2], 0.125f, -EXP_SHIFT));
            float e3 = __expf(fmaf(acc[nb][3], 0.125f, -EXP_SHIFT));
            psum0 += e0 + e1;
            psum1 += e2 + e3;
            __half2 h01, h23;
            h01.x = __float2half(e0); h01.y = __float2half(e1);
            h23.x = __float2half(e2); h23.y = __float2half(e3);
            int col = nw + nb * 8 + tig * 2;
            *(__half2*)((char*)St + (mw + gid)     * PR_STROW + col * 2) = h01;
            *(__half2*)((char*)St + (mw + gid + 8) * PR_STROW + col * 2) = h23;
        }
        __syncthreads();
        #pragma unroll
        for (int t = 0; t < 2; t++) {
            int u = tid + t * 256;
            int row = u >> 4, seg = u & 15;
            uint4 v = *(const uint4*)((char*)St + row * PR_STROW + seg * 16);
            *(uint4*)(g_p + ((size_t)b * NTOK + i0 + row) * NTOK + j * 128 + seg * 8) = v;
        }
        __syncthreads();
    }

    psum0 += __shfl_xor_sync(~0u, psum0, 1);
    psum0 += __shfl_xor_sync(~0u, psum0, 2);
    psum1 += __shfl_xor_sync(~0u, psum1, 1);
    psum1 += __shfl_xor_sync(~0u, psum1, 2);
    if (tig == 0) {
        Sum[(mw + gid) * 4 + (wid & 3)]     = psum0;
        Sum[(mw + gid + 8) * 4 + (wid & 3)] = psum1;
    }
    __syncthreads();
    if (tid < 32) {
        float s = Sum[tid * 4] + Sum[tid * 4 + 1] + Sum[tid * 4 + 2] + Sum[tid * 4 + 3];
        g_inv[(size_t)b * NTOK + i0 + tid] = 1.0f / s;
    }
}

// ---------------------------------------------------------------------------
// Kernel 3: O = inv[row] * (P~ @ V) + x.
// RETILED: 256 thr, 8 warps (2m x 4n), warp tile 64x32 -> ~64 acc regs,
// 2 CTAs/SM = 16 warps/SM (was 12).  CTA tile 128x128 unchanged (same traffic).
// ---------------------------------------------------------------------------
__global__ void __launch_bounds__(256, 2)
av_tc_kernel(const float* __restrict__ x, float* __restrict__ out)
{
    extern __shared__ char dsmem[];
    const uint32_t sb = smem_u32(dsmem);
    float* Inv = (float*)(dsmem + AV_INV);
    const int b = blockIdx.z;
    const int i0 = blockIdx.y * 128, c0 = blockIdx.x * 128;
    const int tid = threadIdx.x;
    const int wid = tid >> 5, lane = tid & 31;
    const int mw = (wid >> 2) * 64, nw = (wid & 3) * 32;

    if (tid < 128) Inv[tid] = g_inv[(size_t)b * NTOK + i0 + tid];

    const __half* pA = g_p + ((size_t)b * NTOK + i0) * NTOK;
    const __half* pB = g_vh + (size_t)b * NTOK * CH + c0;

    const uint32_t a_l = (uint32_t)((lane & 15) * ROW_B + (lane >> 4) * 16);
    const uint32_t b_l = (uint32_t)((lane & 15) * AV_BROW + (lane >> 4) * 16);

    auto load_stage = [&](int chunk, int st) {
        const int k0 = chunk * 64;
        const uint32_t base = sb + (uint32_t)st * AV_STAGE;
        #pragma unroll
        for (int t = 0; t < 4; t++) {               // A: 128 rows x 8 segs = 1024
            int u = tid + t * 256;
            int row = u >> 3, seg = u & 7;
            cp16(base + (uint32_t)(row * ROW_B + seg * 16),
                 pA + (size_t)row * NTOK + k0 + seg * 8);
        }
        #pragma unroll
        for (int t = 0; t < 4; t++) {               // B: 64 rows x 16 segs = 1024
            int u = tid + t * 256;
            int row = u >> 4, seg = u & 15;
            cp16(base + AV_OB + (uint32_t)(row * AV_BROW + seg * 16),
                 pB + (size_t)(k0 + row) * CH + seg * 8);
        }
        CP_COMMIT();
    };

    float acc[4][4][4] = {};                        // 64 regs: mb 4 x n8 4 x ci 4
    load_stage(0, 0);

    for (int c = 0; c < 16; c++) {
        if (c + 1 < 16) load_stage(c + 1, (c + 1) & 1);
        else            CP_COMMIT();
        CP_WAIT1();
        __syncthreads();

        const uint32_t stb = sb + (uint32_t)(c & 1) * AV_STAGE;
        #pragma unroll
        for (int kk = 0; kk < 64; kk += 16) {
            uint32_t bf[2][4];                      // 2 x ldm_x4_trans = 4 n8 frags
            #pragma unroll
            for (int g = 0; g < 2; g++)
                ldm_x4_trans(bf[g],
                    stb + AV_OB + (uint32_t)(kk * AV_BROW + (nw + g * 16) * 2) + b_l);
            #pragma unroll
            for (int mb = 0; mb < 4; mb++) {
                uint32_t af[4];
                ldm_x4(af, stb + (uint32_t)((mw + mb * 16) * ROW_B + kk * 2) + a_l);
                #pragma unroll
                for (int g = 0; g < 2; g++) {
                    mma_f16(acc[mb][g * 2 + 0], af, bf[g] + 0);
                    mma_f16(acc[mb][g * 2 + 1], af, bf[g] + 2);
                }
            }
        }
        __syncthreads();
    }

    const int gid = lane >> 2, tig = lane & 3;
    #pragma unroll
    for (int mb = 0; mb < 4; mb++)
        #pragma unroll
        for (int h = 0; h < 2; h++) {
            int lrow = mw + mb * 16 + gid + h * 8;
            float iv = Inv[lrow];
            int row = i0 + lrow;
            #pragma unroll
            for (int nb = 0; nb < 4; nb++) {
                int col = c0 + nw + nb * 8 + tig * 2;
                size_t o = ((size_t)b * NTOK + row) * CH + col;
                float2 xv = *(const float2*)(x + o);
                float2 ov;
                ov.x = fmaf(acc[mb][nb][h * 2 + 0], iv, xv.x);
                ov.y = fmaf(acc[mb][nb][h * 2 + 1], iv, xv.y);
                *(float2*)(out + o) = ov;
            }
        }
}

// ---------------------------------------------------------------------------
extern "C" void kernel_launch(void* const* d_in, const int* in_sizes, int n_in,
                              void* d_out, int out_size)
{
    const float* x  = (const float*)d_in[0];
    const float* wq = (const float*)d_in[1];
    const float* bq = (const float*)d_in[2];
    const float* wk = (const float*)d_in[3];
    const float* bk = (const float*)d_in[4];
    const float* wv = (const float*)d_in[5];
    const float* bv = (const float*)d_in[6];
    float* out = (float*)d_out;

    cudaFuncSetAttribute(qkv_tc_kernel, cudaFuncAttributeMaxDynamicSharedMemorySize, SMEM_B);
    cudaFuncSetAttribute(probs_kernel,  cudaFuncAttributeMaxDynamicSharedMemorySize, PR_SMEM);
    cudaFuncSetAttribute(av_tc_kernel,  cudaFuncAttributeMaxDynamicSharedMemorySize, AV_SMEM);

    conv_kernel<<<CONVX_BLOCKS + CONVW_BLOCKS, 256>>>(x, wq, wk, wv);
    qkv_tc_kernel<<<dim3(5, 256), 128, SMEM_B>>>(bq, bk, bv);
    probs_kernel<<<dim3(32, 32), 256, PR_SMEM>>>();
    av_tc_kernel<<<dim3(4, 8, 32), 256, AV_SMEM>>>(x, out);
}

// round 17
// speedup vs baseline: 1.0528x; 1.0528x over previous
#include <cuda_runtime.h>
#include <cuda_fp16.h>
#include <cstdint>

#define BATCH 32
#define NTOK  1024
#define CH    512
#define DQKD  64

// ---------------------------------------------------------------------------
// Device-global scratch (fp16 operands)
// ---------------------------------------------------------------------------
__device__ __align__(128) __half g_wt[640 * CH];                      // W^T [n][k]
__device__ __align__(128) __half g_qh[(size_t)BATCH * NTOK * DQKD];
__device__ __align__(128) __half g_kh[(size_t)BATCH * NTOK * DQKD];
__device__ __align__(128) __half g_vh[(size_t)BATCH * NTOK * CH];     // V [b][m][c]
__device__ __align__(128) __half g_p[(size_t)BATCH * NTOK * NTOK];    // 64 MB P~ (unnormalized)
__device__ __align__(128) float  g_inv[(size_t)BATCH * NTOK];         // 1/rowsum

// ---------------------------------------------------------------------------
// PTX helpers (baseline ISA: compiles for compute_103)
// ---------------------------------------------------------------------------
__device__ __forceinline__ uint32_t smem_u32(const void* p) {
    uint32_t a;
    asm("{ .reg .u64 t; cvta.to.shared.u64 t, %1; cvt.u32.u64 %0, t; }" : "=r"(a) : "l"(p));
    return a;
}
__device__ __forceinline__ void cp16(uint32_t dst, const void* src) {
    asm volatile("cp.async.cg.shared.global [%0], [%1], 16;" :: "r"(dst), "l"(src));
}
#define CP_COMMIT() asm volatile("cp.async.commit_group;" ::: "memory")
#define CP_WAIT1()  asm volatile("cp.async.wait_group 1;" ::: "memory")

__device__ __forceinline__ void ldm_x4(uint32_t* r, uint32_t addr) {
    asm volatile("ldmatrix.sync.aligned.m8n8.x4.shared.b16 {%0,%1,%2,%3}, [%4];"
                 : "=r"(r[0]), "=r"(r[1]), "=r"(r[2]), "=r"(r[3]) : "r"(addr));
}
__device__ __forceinline__ void ldm_x2(uint32_t* r, uint32_t addr) {
    asm volatile("ldmatrix.sync.aligned.m8n8.x2.shared.b16 {%0,%1}, [%2];"
                 : "=r"(r[0]), "=r"(r[1]) : "r"(addr));
}
__device__ __forceinline__ void ldm_x4_trans(uint32_t* r, uint32_t addr) {
    asm volatile("ldmatrix.sync.aligned.m8n8.x4.trans.shared.b16 {%0,%1,%2,%3}, [%4];"
                 : "=r"(r[0]), "=r"(r[1]), "=r"(r[2]), "=r"(r[3]) : "r"(addr));
}
__device__ __forceinline__ void mma_f16(float* c, const uint32_t* a, const uint32_t* b) {
    asm volatile(
        "mma.sync.aligned.m16n8k16.row.col.f32.f16.f16.f32 "
        "{%0,%1,%2,%3}, {%4,%5,%6,%7}, {%8,%9}, {%0,%1,%2,%3};"
        : "+f"(c[0]), "+f"(c[1]), "+f"(c[2]), "+f"(c[3])
        : "r"(a[0]), "r"(a[1]), "r"(a[2]), "r"(a[3]), "r"(b[0]), "r"(b[1]));
}

// ---------------------------------------------------------------------------
// Tiling constants
// ---------------------------------------------------------------------------
#define ROW_B   144                  // 64 fp16 rows (probs/av A tiles)
#define TILE_B  (128 * ROW_B)        // 18432

// qkv: BK=32.  A = x in f32: rows 40 f32 = 160 B (conflict-free LDS.64).
//             B = W^T fp16: rows 32 fp16 = 64 B + 16 pad = 80 B.
#define QK_AROWF  40                 // floats per padded A row
#define QK_AROWB  160
#define QK_ATILE  (128 * QK_AROWB)   // 20480
#define QK_BROW   80
#define QK_BTILE  (128 * QK_BROW)    // 10240
#define QK_STAGE  (QK_ATILE + QK_BTILE)   // 30720
#define QK_SMEM   (2 * QK_STAGE)          // 61440

// av: A = P [128 tok][64 k] rows 144 B; B = V [64 k][128 c] rows 272 B
#define AV_BROW   272
#define AV_BTILE  (64 * AV_BROW)     // 17408
#define AV_OB     TILE_B
#define AV_STAGE  (TILE_B + AV_BTILE)   // 35840
#define AV_INV    (2 * AV_STAGE)        // 71680 (128 floats)
#define AV_SMEM   (AV_INV + 512)        // 72192

// probs: q [32][64] rows 144 B; k double-buffered [128][64] rows 144 B;
// fp16 staging [32 rows][272 B]; partial sums [32 rows][4 warps]
#define PR_Q      0
#define PR_QSZ    (32 * ROW_B)                    // 4608
#define PR_K      PR_QSZ
#define PR_KSZ    (128 * ROW_B)                   // 18432
#define PR_ST     (PR_K + 2 * PR_KSZ)             // 41472
#define PR_STROW  272
#define PR_STSZ   (32 * PR_STROW)                 // 8704
#define PR_SUM    (PR_ST + PR_STSZ)               // 50176
#define PR_SMEM   (PR_SUM + 512)                  // 50688

#define EXP_SHIFT 4.0f

// ---------------------------------------------------------------------------
// Prep kernel: W^T fp16 only (x conversion is fused into qkv now)
// ---------------------------------------------------------------------------
__global__ void convw_kernel(const float* __restrict__ wq,
                             const float* __restrict__ wk,
                             const float* __restrict__ wv)
{
    int idx = blockIdx.x * 256 + threadIdx.x;     // 640*512
    int n = idx >> 9, k = idx & 511;
    float v;
    if (n < 64)        v = wq[k * DQKD + n];
    else if (n < 128)  v = wk[k * DQKD + (n - 64)];
    else               v = wv[k * CH + (n - 128)];
    g_wt[idx] = __float2half(v);
}

// ---------------------------------------------------------------------------
// Kernel 1: QKV projection with fused x f32->fp16 conversion.
// M=32768, N=640, K=512. grid (5 n-tiles fastest, 256 m-tiles).
// 128 thr, 4 warps (2x2), warp tile 64x64, 3 CTAs/SM, BK=32, 2-stage.
// A staged as f32; A-fragments built via LDS.64 + cvt (no ldmatrix for A).
// ---------------------------------------------------------------------------
__global__ void __launch_bounds__(128, 3)
qkv_tc_kernel(const float* __restrict__ x,
              const float* __restrict__ bq, const float* __restrict__ bk,
              const float* __restrict__ bv)
{
    extern __shared__ char dsmem[];
    const uint32_t sb = smem_u32(dsmem);
    float* Af = (float*)dsmem;                     // f32 A stages (viewed per stage)
    const int m0 = blockIdx.y * 128;
    const int n0 = blockIdx.x * 128;
    const int tid = threadIdx.x;
    const int wid = tid >> 5, lane = tid & 31;
    const int mw = (wid >> 1) * 64, nw = (wid & 1) * 64;
    const int gid = lane >> 2, tig = lane & 3;

    const float* gA = x + (size_t)m0 * CH;
    const __half* gB = g_wt + (size_t)n0 * CH;

    const uint32_t b_l = (uint32_t)((lane & 7) * QK_BROW + ((lane >> 3) & 1) * 16);

    auto load_stage = [&](int chunk, int st) {
        const int k0 = chunk * 32;
        const uint32_t base = sb + (uint32_t)st * QK_STAGE;
        #pragma unroll
        for (int t = 0; t < 8; t++) {              // A: 128 rows x 8 segs of 16 B (f32)
            int u = tid + t * 128;
            int row = u >> 3, seg = u & 7;
            cp16(base + (uint32_t)(row * QK_AROWB + seg * 16),
                 gA + (size_t)row * CH + k0 + seg * 4);
        }
        #pragma unroll
        for (int t = 0; t < 4; t++) {              // B: 128 rows x 4 segs of 16 B (fp16)
            int u = tid + t * 128;
            int row = u >> 2, seg = u & 3;
            cp16(base + QK_ATILE + (uint32_t)(row * QK_BROW + seg * 16),
                 gB + (size_t)row * CH + k0 + seg * 8);
        }
        CP_COMMIT();
    };

    float acc[4][8][4] = {};
    load_stage(0, 0);

    for (int c = 0; c < 16; c++) {
        if (c + 1 < 16) load_stage(c + 1, (c + 1) & 1);
        else            CP_COMMIT();
        CP_WAIT1();
        __syncthreads();

        const uint32_t stb = sb + (uint32_t)(c & 1) * QK_STAGE;
        const float* As = Af + (size_t)(c & 1) * (QK_STAGE / 4);
        #pragma unroll
        for (int kk = 0; kk < 32; kk += 16) {
            uint32_t bf[8][2];
            #pragma unroll
            for (int nb = 0; nb < 8; nb++)
                ldm_x2(bf[nb], stb + QK_ATILE +
                       (uint32_t)((nw + nb * 8) * QK_BROW + kk * 2) + b_l);
            #pragma unroll
            for (int mb = 0; mb < 4; mb++) {
                int r0 = mw + mb * 16 + gid;
                const float* pr0 = As + r0 * QK_AROWF + kk + 2 * tig;
                const float* pr8 = pr0 + 8 * QK_AROWF;
                float2 v0 = *(const float2*)(pr0);       // [r][kk+2tig..+1]
                float2 v1 = *(const float2*)(pr8);       // [r+8][..]
                float2 v2 = *(const float2*)(pr0 + 8);   // [r][kk+8+2tig..]
                float2 v3 = *(const float2*)(pr8 + 8);
                uint32_t af[4];
                __half2 h;
                h = __floats2half2_rn(v0.x, v0.y); af[0] = *(uint32_t*)&h;
                h = __floats2half2_rn(v1.x, v1.y); af[1] = *(uint32_t*)&h;
                h = __floats2half2_rn(v2.x, v2.y); af[2] = *(uint32_t*)&h;
                h = __floats2half2_rn(v3.x, v3.y); af[3] = *(uint32_t*)&h;
                #pragma unroll
                for (int nb = 0; nb < 8; nb++)
                    mma_f16(acc[mb][nb], af, bf[nb]);
            }
        }
        __syncthreads();
    }

    #pragma unroll
    for (int mb = 0; mb < 4; mb++)
        #pragma unroll
        for (int nb = 0; nb < 8; nb++)
            #pragma unroll
            for (int h = 0; h < 2; h++) {
                int row = m0 + mw + mb * 16 + gid + h * 8;
                int col = n0 + nw + nb * 8 + tig * 2;
                float b0, b1;
                if (col < 64)       { b0 = bq[col];        b1 = bq[col + 1]; }
                else if (col < 128) { b0 = bk[col - 64];   b1 = bk[col - 63]; }
                else                { b0 = bv[col - 128];  b1 = bv[col - 127]; }
                __half2 hv;
                hv.x = __float2half(acc[mb][nb][h * 2 + 0] + b0);
                hv.y = __float2half(acc[mb][nb][h * 2 + 1] + b1);
                if (col < 64)
                    *(__half2*)(g_qh + (size_t)row * DQKD + col) = hv;
                else if (col < 128)
                    *(__half2*)(g_kh + (size_t)row * DQKD + (col - 64)) = hv;
                else
                    *(__half2*)(g_vh + (size_t)row * CH + (col - 128)) = hv;
            }
}

// ---------------------------------------------------------------------------
// Kernel 2: FUSED scores + exp -> unnormalized P~ (fp16) + row inv-sums.
// (unchanged from R13)
// ---------------------------------------------------------------------------
__global__ void __launch_bounds__(256, 4)
probs_kernel()
{
    extern __shared__ char dsmem[];
    const uint32_t sb = smem_u32(dsmem);
    __half* St = (__half*)(dsmem + PR_ST);
    float* Sum = (float*)(dsmem + PR_SUM);

    const int tid = threadIdx.x;
    const int wid = tid >> 5, lane = tid & 31;
    const int b = blockIdx.y;
    const int i0 = blockIdx.x * 32;

    const __half* gq = g_qh + ((size_t)b * NTOK + i0) * DQKD;
    const __half* gk = g_kh + (size_t)b * NTOK * DQKD;

    {
        int row = tid >> 3, seg = tid & 7;
        cp16(sb + PR_Q + (uint32_t)(row * ROW_B + seg * 16),
             gq + (size_t)row * DQKD + seg * 8);
        #pragma unroll
        for (int t = 0; t < 4; t++) {
            int u = tid + t * 256;
            int r = u >> 3, s = u & 7;
            cp16(sb + PR_K + (uint32_t)(r * ROW_B + s * 16),
                 gk + (size_t)r * DQKD + s * 8);
        }
        CP_COMMIT();
    }

    const int mw = (wid >> 2) * 16;
    const int nw = (wid & 3) * 32;
    const uint32_t a_l = (uint32_t)((lane & 15) * ROW_B + (lane >> 4) * 16);
    const uint32_t b_l = (uint32_t)((lane & 7) * ROW_B + ((lane >> 3) & 1) * 16);
    const int gid = lane >> 2, tig = lane & 3;

    uint32_t af[4][4];
    bool a_loaded = false;
    float psum0 = 0.f, psum1 = 0.f;

    for (int j = 0; j < 8; j++) {
        if (j + 1 < 8) {
            const __half* gkn = gk + (size_t)(j + 1) * 128 * DQKD;
            const uint32_t kb = sb + PR_K + (uint32_t)(((j + 1) & 1) * PR_KSZ);
            #pragma unroll
            for (int t = 0; t < 4; t++) {
                int u = tid + t * 256;
                int r = u >> 3, s = u & 7;
                cp16(kb + (uint32_t)(r * ROW_B + s * 16), gkn + (size_t)r * DQKD + s * 8);
            }
            CP_COMMIT();
        } else CP_COMMIT();
        CP_WAIT1();
        __syncthreads();

        if (!a_loaded) {
            #pragma unroll
            for (int kk = 0; kk < 4; kk++)
                ldm_x4(af[kk], sb + PR_Q + (uint32_t)(mw * ROW_B + kk * 32) + a_l);
            a_loaded = true;
        }

        const uint32_t kbb = sb + PR_K + (uint32_t)((j & 1) * PR_KSZ);
        float acc[4][4] = {};
        #pragma unroll
        for (int kk = 0; kk < 4; kk++) {
            #pragma unroll
            for (int nb = 0; nb < 4; nb++) {
                uint32_t bf[2];
                ldm_x2(bf, kbb + (uint32_t)((nw + nb * 8) * ROW_B + kk * 32) + b_l);
                mma_f16(acc[nb], af[kk], bf);
            }
        }
        #pragma unroll
        for (int nb = 0; nb < 4; nb++) {
            float e0 = __expf(fmaf(acc[nb][0], 0.125f, -EXP_SHIFT));
            float e1 = __expf(fmaf(acc[nb][1], 0.125f, -EXP_SHIFT));
            float e2 = __expf(fmaf(acc[nb][2], 0.125f, -EXP_SHIFT));
            float e3 = __expf(fmaf(acc[nb][3], 0.125f, -EXP_SHIFT));
            psum0 += e0 + e1;
            psum1 += e2 + e3;
            __half2 h01, h23;
            h01.x = __float2half(e0); h01.y = __float2half(e1);
            h23.x = __float2half(e2); h23.y = __float2half(e3);
            int col = nw + nb * 8 + tig * 2;
            *(__half2*)((char*)St + (mw + gid)     * PR_STROW + col * 2) = h01;
            *(__half2*)((char*)St + (mw + gid + 8) * PR_STROW + col * 2) = h23;
        }
        __syncthreads();
        #pragma unroll
        for (int t = 0; t < 2; t++) {
            int u = tid + t * 256;
            int row = u >> 4, seg = u & 15;
            uint4 v = *(const uint4*)((char*)St + row * PR_STROW + seg * 16);
            *(uint4*)(g_p + ((size_t)b * NTOK + i0 + row) * NTOK + j * 128 + seg * 8) = v;
        }
        __syncthreads();
    }

    psum0 += __shfl_xor_sync(~0u, psum0, 1);
    psum0 += __shfl_xor_sync(~0u, psum0, 2);
    psum1 += __shfl_xor_sync(~0u, psum1, 1);
    psum1 += __shfl_xor_sync(~0u, psum1, 2);
    if (tig == 0) {
        Sum[(mw + gid) * 4 + (wid & 3)]     = psum0;
        Sum[(mw + gid + 8) * 4 + (wid & 3)] = psum1;
    }
    __syncthreads();
    if (tid < 32) {
        float s = Sum[tid * 4] + Sum[tid * 4 + 1] + Sum[tid * 4 + 2] + Sum[tid * 4 + 3];
        g_inv[(size_t)b * NTOK + i0 + tid] = 1.0f / s;
    }
}

// ---------------------------------------------------------------------------
// Kernel 3: O = inv[row] * (P~ @ V) + x.  R13 best config:
// 128 thr, 4 warps (2x2), warp tile 64x64, 3 CTAs/SM (12 warps).
// ---------------------------------------------------------------------------
__global__ void __launch_bounds__(128, 3)
av_tc_kernel(const float* __restrict__ x, float* __restrict__ out)
{
    extern __shared__ char dsmem[];
    const uint32_t sb = smem_u32(dsmem);
    float* Inv = (float*)(dsmem + AV_INV);
    const int b = blockIdx.z;
    const int i0 = blockIdx.y * 128, c0 = blockIdx.x * 128;
    const int tid = threadIdx.x;
    const int wid = tid >> 5, lane = tid & 31;
    const int mw = (wid >> 1) * 64, nw = (wid & 1) * 64;

    Inv[tid] = g_inv[(size_t)b * NTOK + i0 + tid];

    const __half* pA = g_p + ((size_t)b * NTOK + i0) * NTOK;
    const __half* pB = g_vh + (size_t)b * NTOK * CH + c0;

    const uint32_t a_l = (uint32_t)((lane & 15) * ROW_B + (lane >> 4) * 16);
    const uint32_t b_l = (uint32_t)((lane & 15) * AV_BROW + (lane >> 4) * 16);

    auto load_stage = [&](int chunk, int st) {
        const int k0 = chunk * 64;
        const uint32_t base = sb + (uint32_t)st * AV_STAGE;
        #pragma unroll
        for (int t = 0; t < 8; t++) {
            int u = tid + t * 128;
            int row = u >> 3, seg = u & 7;
            cp16(base + (uint32_t)(row * ROW_B + seg * 16),
                 pA + (size_t)row * NTOK + k0 + seg * 8);
        }
        #pragma unroll
        for (int t = 0; t < 8; t++) {
            int u = tid + t * 128;
            int row = u >> 4, seg = u & 15;
            cp16(base + AV_OB + (uint32_t)(row * AV_BROW + seg * 16),
                 pB + (size_t)(k0 + row) * CH + seg * 8);
        }
        CP_COMMIT();
    };

    float acc[4][8][4] = {};
    load_stage(0, 0);

    for (int c = 0; c < 16; c++) {
        if (c + 1 < 16) load_stage(c + 1, (c + 1) & 1);
        else            CP_COMMIT();
        CP_WAIT1();
        __syncthreads();

        const uint32_t stb = sb + (uint32_t)(c & 1) * AV_STAGE;
        #pragma unroll
        for (int kk = 0; kk < 64; kk += 16) {
            uint32_t bf[4][4];
            #pragma unroll
            for (int nb2 = 0; nb2 < 4; nb2++)
                ldm_x4_trans(bf[nb2],
                    stb + AV_OB + (uint32_t)(kk * AV_BROW + (nw + nb2 * 16) * 2) + b_l);
            #pragma unroll
            for (int mb = 0; mb < 4; mb++) {
                uint32_t af[4];
                ldm_x4(af, stb + (uint32_t)((mw + mb * 16) * ROW_B + kk * 2) + a_l);
                #pragma unroll
                for (int nb2 = 0; nb2 < 4; nb2++) {
                    mma_f16(acc[mb][nb2 * 2 + 0], af, bf[nb2] + 0);
                    mma_f16(acc[mb][nb2 * 2 + 1], af, bf[nb2] + 2);
                }
            }
        }
        __syncthreads();
    }

    const int gid = lane >> 2, tig = lane & 3;
    #pragma unroll
    for (int mb = 0; mb < 4; mb++)
        #pragma unroll
        for (int h = 0; h < 2; h++) {
            int lrow = mw + mb * 16 + gid + h * 8;
            float iv = Inv[lrow];
            int row = i0 + lrow;
            #pragma unroll
            for (int nb = 0; nb < 8; nb++) {
                int col = c0 + nw + nb * 8 + tig * 2;
                size_t o = ((size_t)b * NTOK + row) * CH + col;
                float2 xv = *(const float2*)(x + o);
                float2 ov;
                ov.x = fmaf(acc[mb][nb][h * 2 + 0], iv, xv.x);
                ov.y = fmaf(acc[mb][nb][h * 2 + 1], iv, xv.y);
                *(float2*)(out + o) = ov;
            }
        }
}

// ---------------------------------------------------------------------------
extern "C" void kernel_launch(void* const* d_in, const int* in_sizes, int n_in,
                              void* d_out, int out_size)
{
    const float* x  = (const float*)d_in[0];
    const float* wq = (const float*)d_in[1];
    const float* bq = (const float*)d_in[2];
    const float* wk = (const float*)d_in[3];
    const float* bk = (const float*)d_in[4];
    const float* wv = (const float*)d_in[5];
    const float* bv = (const float*)d_in[6];
    float* out = (float*)d_out;

    cudaFuncSetAttribute(qkv_tc_kernel, cudaFuncAttributeMaxDynamicSharedMemorySize, QK_SMEM);
    cudaFuncSetAttribute(probs_kernel,  cudaFuncAttributeMaxDynamicSharedMemorySize, PR_SMEM);
    cudaFuncSetAttribute(av_tc_kernel,  cudaFuncAttributeMaxDynamicSharedMemorySize, AV_SMEM);

    convw_kernel<<<1280, 256>>>(wq, wk, wv);
    qkv_tc_kernel<<<dim3(5, 256), 128, QK_SMEM>>>(x, bq, bk, bv);
    probs_kernel<<<dim3(32, 32), 256, PR_SMEM>>>();
    av_tc_kernel<<<dim3(4, 8, 32), 128, AV_SMEM>>>(x, out);
}